// round 1
// baseline (speedup 1.0000x reference)
#include <cuda_runtime.h>
#include <math.h>

// ---------------- problem constants ----------------
#define BB   2
#define NTOK 577
#define DIMM 512
#define HH   8
#define DHH  64
#define NCC  145     // ceil(577/4) compressed blocks
#define NSB  10      // ceil(577/64) select blocks
#define KSEL 4
#define SWIN 32
#define MLPD 2048
#define NCLS 1000
#define BN   (BB*NTOK)    // 1154

#define ACT_NONE 0
#define ACT_GELU 1
#define ACT_SIG  2

// ---------------- device scratch (no allocations allowed) ----------------
__device__ float g_x   [BN*DIMM];
__device__ float g_h   [BN*DIMM];
__device__ float g_q   [BN*DIMM];
__device__ float g_k   [BN*DIMM];
__device__ float g_v   [BN*DIMM];
__device__ float g_gate[BN*24];
__device__ float g_ck  [BB*HH*NCC*DHH];
__device__ float g_cv  [BB*HH*NCC*DHH];
__device__ float g_outc[BB*HH*NTOK*DHH];
__device__ float g_outs[BB*HH*NTOK*DHH];
__device__ int   g_selb[BB*HH*NTOK*KSEL];
__device__ float g_attn[BN*DIMM];
__device__ float g_mlp [BN*MLPD];
__device__ float g_hb  [BB*DIMM];

// ---------------- helpers ----------------
__device__ __forceinline__ float block_sum256(float v, float* red) {
    int t = threadIdx.x;
    __syncthreads();
    red[t] = v; __syncthreads();
    for (int s = 128; s > 0; s >>= 1) { if (t < s) red[t] += red[t + s]; __syncthreads(); }
    float r = red[0]; __syncthreads();
    return r;
}
__device__ __forceinline__ float block_max256(float v, float* red) {
    int t = threadIdx.x;
    __syncthreads();
    red[t] = v; __syncthreads();
    for (int s = 128; s > 0; s >>= 1) { if (t < s) red[t] = fmaxf(red[t], red[t + s]); __syncthreads(); }
    float r = red[0]; __syncthreads();
    return r;
}
__device__ __forceinline__ float gelu_tanh(float x) {
    float x3 = x * x * x;
    return 0.5f * x * (1.0f + tanhf(0.7978845608028654f * (x + 0.044715f * x3)));
}

// ---------------- patch embed + cls + pos ----------------
__global__ void patch_embed_kernel(const float* __restrict__ img,
                                   const float* __restrict__ pw,
                                   const float* __restrict__ pb,
                                   const float* __restrict__ pos,
                                   const float* __restrict__ cls,
                                   float* __restrict__ x) {
    int t = blockIdx.x % NTOK;
    int b = blockIdx.x / NTOK;
    for (int d = threadIdx.x; d < DIMM; d += blockDim.x) {
        float v;
        if (t == 0) {
            v = cls[d];
        } else {
            int p = t - 1;
            int ii = p / 24, jj = p % 24;
            v = pb[d];
            #pragma unroll
            for (int c = 0; c < 3; c++)
                v += img[((b * 3 + c) * 24 + ii) * 24 + jj] * pw[c * DIMM + d];
        }
        x[((size_t)(b * NTOK + t)) * DIMM + d] = v + pos[(size_t)t * DIMM + d];
    }
}

// ---------------- layernorm (row length 512, block 256) ----------------
__global__ void ln_kernel(const float* __restrict__ in, long strideIn,
                          float* __restrict__ out,
                          const float* __restrict__ g, const float* __restrict__ bb) {
    __shared__ float red[256];
    int r = blockIdx.x;
    const float* row = in + (size_t)r * strideIn;
    int t = threadIdx.x;
    float a0 = row[t], a1 = row[t + 256];
    float mean = block_sum256(a0 + a1, red) * (1.0f / 512.0f);
    float d0 = a0 - mean, d1 = a1 - mean;
    float var = block_sum256(d0 * d0 + d1 * d1, red) * (1.0f / 512.0f);
    float inv = rsqrtf(var + 1e-5f);
    out[(size_t)r * DIMM + t]       = d0 * inv * g[t] + bb[t];
    out[(size_t)r * DIMM + t + 256] = d1 * inv * g[t + 256] + bb[t + 256];
}

// ---------------- generic SGEMM: C = act(A@W + bias) + res ----------------
// A: MxK row-major, W: KxN row-major. K must be multiple of 16.
// block (16,16), tile 64x64, 4x4 per thread.
__global__ __launch_bounds__(256) void sgemm_kernel(
    const float* __restrict__ A, const float* __restrict__ W,
    const float* __restrict__ bias, const float* __restrict__ res,
    float* __restrict__ C, int M, int Nn, int K, int act)
{
    __shared__ float As[16][65];
    __shared__ float Bs[16][64];
    int tx = threadIdx.x, ty = threadIdx.y;
    int tid = ty * 16 + tx;
    int row0 = blockIdx.y * 64, col0 = blockIdx.x * 64;
    float acc[4][4];
    #pragma unroll
    for (int i = 0; i < 4; i++)
        #pragma unroll
        for (int j = 0; j < 4; j++) acc[i][j] = 0.f;

    int akk = tid & 15;            // k within tile
    int amm0 = tid >> 4;           // row within tile (step 16)
    for (int k0 = 0; k0 < K; k0 += 16) {
        #pragma unroll
        for (int l = 0; l < 4; l++) {
            int mm = amm0 + l * 16;
            int r = row0 + mm;
            As[akk][mm] = (r < M) ? A[(size_t)r * K + k0 + akk] : 0.f;
        }
        #pragma unroll
        for (int l = 0; l < 4; l++) {
            int e = tid + l * 256;
            int kk = e >> 6, nn = e & 63;
            int c = col0 + nn;
            Bs[kk][nn] = (c < Nn) ? W[(size_t)(k0 + kk) * Nn + c] : 0.f;
        }
        __syncthreads();
        #pragma unroll
        for (int kk = 0; kk < 16; kk++) {
            float av[4], bv[4];
            #pragma unroll
            for (int i = 0; i < 4; i++) av[i] = As[kk][ty * 4 + i];
            #pragma unroll
            for (int j = 0; j < 4; j++) bv[j] = Bs[kk][tx * 4 + j];
            #pragma unroll
            for (int i = 0; i < 4; i++)
                #pragma unroll
                for (int j = 0; j < 4; j++) acc[i][j] += av[i] * bv[j];
        }
        __syncthreads();
    }
    #pragma unroll
    for (int i = 0; i < 4; i++) {
        int r = row0 + ty * 4 + i;
        if (r >= M) continue;
        #pragma unroll
        for (int j = 0; j < 4; j++) {
            int c = col0 + tx * 4 + j;
            if (c >= Nn) continue;
            float v = acc[i][j];
            if (bias) v += bias[c];
            if (act == ACT_GELU) v = gelu_tanh(v);
            else if (act == ACT_SIG) v = 1.0f / (1.0f + expf(-v));
            if (res) v += res[(size_t)r * Nn + c];
            C[(size_t)r * Nn + c] = v;
        }
    }
}

// ---------------- compress projection: ck/cv = (gather(k)+pe) @ Wc ----------------
// grid B*H*NCC blocks, 64 threads
__global__ void compress_kernel(const float* __restrict__ kin,
                                const float* __restrict__ pe,     // [16,64]
                                const float* __restrict__ Wc,     // [1024,64]
                                float* __restrict__ out) {        // [B*H*NCC,64]
    __shared__ float kw[1024];
    int j  = blockIdx.x % NCC;
    int bh = blockIdx.x / NCC;
    int h = bh % HH, b = bh / HH;
    int tid = threadIdx.x;
    for (int e = tid; e < 1024; e += 64) {
        int jj = e >> 6, d = e & 63;
        int tok = j * 4 + jj;
        float kv = (tok < NTOK) ? kin[((size_t)(b * NTOK + tok)) * DIMM + h * DHH + d] : 0.f;
        kw[e] = kv + pe[jj * DHH + d];
    }
    __syncthreads();
    float acc = 0.f;
    for (int e = 0; e < 1024; e++) acc += kw[e] * Wc[(size_t)e * DHH + tid];
    out[((size_t)blockIdx.x) * DHH + tid] = acc;
}

// ---------------- compressed attention + top-k block select ----------------
// grid B*H*NTOK blocks, 256 threads
__global__ __launch_bounds__(256) void cattn_kernel(
    const float* __restrict__ q, const float* __restrict__ ck,
    const float* __restrict__ cv, float* __restrict__ outc,
    int* __restrict__ selb)
{
    __shared__ float qs[64];
    __shared__ float sc[NCC];
    __shared__ float red[256];
    __shared__ float imp[NSB];
    int gi = blockIdx.x;
    int i  = gi % NTOK;
    int bh = gi / NTOK;
    int h = bh % HH, b = bh / HH;
    int tid = threadIdx.x;
    if (tid < 64) qs[tid] = q[((size_t)(b * NTOK + i)) * DIMM + h * DHH + tid];
    __syncthreads();
    const float* ckb = ck + (size_t)bh * NCC * DHH;
    for (int j = tid; j < NCC; j += 256) {
        const float* ckj = ckb + j * DHH;
        float a = 0.f;
        #pragma unroll
        for (int d = 0; d < 64; d++) a += qs[d] * ckj[d];
        sc[j] = a * 0.125f;
    }
    __syncthreads();
    float m = -1e30f;
    for (int j = tid; j < NCC; j += 256) m = fmaxf(m, sc[j]);
    float mx = block_max256(m, red);
    float s = 0.f;
    for (int j = tid; j < NCC; j += 256) { float e = expf(sc[j] - mx); sc[j] = e; s += e; }
    float tot = block_sum256(s, red);
    float inv = 1.0f / tot;
    for (int j = tid; j < NCC; j += 256) sc[j] *= inv;
    __syncthreads();
    // importance per select-block (deterministic ascending-j sum)
    if (tid < NSB) {
        float a = 0.f;
        for (int j = 0; j < NCC; j++) {
            int c = (j * 4 + 8) >> 6; if (c > NSB - 1) c = NSB - 1;
            if (c == tid) a += sc[j];
        }
        imp[tid] = a;
    }
    __syncthreads();
    if (tid == 0) {
        float tmp[NSB];
        #pragma unroll
        for (int t = 0; t < NSB; t++) tmp[t] = imp[t];
        #pragma unroll
        for (int t = 0; t < KSEL; t++) {
            float best = -1e30f; int bi = 0;
            #pragma unroll
            for (int sb = 0; sb < NSB; sb++)
                if (tmp[sb] > best) { best = tmp[sb]; bi = sb; }
            selb[(size_t)gi * KSEL + t] = bi;
            tmp[bi] = -2e30f;
        }
    }
    if (tid < 64) {
        const float* cvb = cv + (size_t)bh * NCC * DHH;
        float a = 0.f;
        for (int j = 0; j < NCC; j++) a += sc[j] * cvb[j * DHH + tid];
        outc[(size_t)gi * DHH + tid] = a;
    }
}

// ---------------- selected-block attention ----------------
// grid B*H*NTOK blocks, 256 threads (4 blocks x 64 tokens)
__global__ __launch_bounds__(256) void sattn_kernel(
    const float* __restrict__ q, const float* __restrict__ k,
    const float* __restrict__ v, const int* __restrict__ selb,
    float* __restrict__ outs)
{
    __shared__ float qs[64];
    __shared__ float ss[256];
    __shared__ float red[256];
    __shared__ int   tks[256];
    int gi = blockIdx.x;
    int i  = gi % NTOK;
    int bh = gi / NTOK;
    int h = bh % HH, b = bh / HH;
    int tid = threadIdx.x;
    if (tid < 64) qs[tid] = q[((size_t)(b * NTOK + i)) * DIMM + h * DHH + tid];
    int sblk = selb[(size_t)gi * KSEL + (tid >> 6)];
    __syncthreads();
    int tok = sblk * 64 + (tid & 63);
    bool valid = (tok < NTOK);
    int tk = valid ? tok : (NTOK - 1);
    tks[tid] = tk;
    const float* kp = k + ((size_t)(b * NTOK + tk)) * DIMM + h * DHH;
    float a = 0.f;
    #pragma unroll
    for (int d = 0; d < 64; d++) a += qs[d] * kp[d];
    float sval = valid ? a * 0.125f : -1e30f;
    ss[tid] = sval;
    float mx = block_max256(sval, red);
    float e = expf(sval - mx);
    float tot = block_sum256(e, red);
    ss[tid] = e / tot;
    __syncthreads();
    if (tid < 64) {
        float acc = 0.f;
        for (int t = 0; t < 256; t++)
            acc += ss[t] * v[((size_t)(b * NTOK + tks[t])) * DIMM + h * DHH + tid];
        outs[(size_t)gi * DHH + tid] = acc;
    }
}

// ---------------- sliding window attention + gate combine ----------------
// grid B*H*NTOK blocks, 64 threads
__global__ void wcomb_kernel(const float* __restrict__ q, const float* __restrict__ k,
                             const float* __restrict__ v,
                             const float* __restrict__ outc, const float* __restrict__ outs,
                             const float* __restrict__ gate, float* __restrict__ attn)
{
    __shared__ float qs[64];
    __shared__ float sw[SWIN];
    __shared__ int   pcs[SWIN];
    int gi = blockIdx.x;
    int i  = gi % NTOK;
    int bh = gi / NTOK;
    int h = bh % HH, b = bh / HH;
    int tid = threadIdx.x;
    qs[tid] = q[((size_t)(b * NTOK + i)) * DIMM + h * DHH + tid];
    __syncthreads();
    if (tid < SWIN) {
        int pos = i + tid - SWIN / 2;
        bool valid = (pos >= 0) && (pos < NTOK);
        int p = pos < 0 ? 0 : (pos > NTOK - 1 ? NTOK - 1 : pos);
        pcs[tid] = p;
        const float* kp = k + ((size_t)(b * NTOK + p)) * DIMM + h * DHH;
        float a = 0.f;
        #pragma unroll
        for (int d = 0; d < 64; d++) a += qs[d] * kp[d];
        sw[tid] = valid ? a * 0.125f : -1e30f;
    }
    __syncthreads();
    float mx = -1e30f;
    #pragma unroll
    for (int w = 0; w < SWIN; w++) mx = fmaxf(mx, sw[w]);
    float s = 0.f;
    #pragma unroll
    for (int w = 0; w < SWIN; w++) s += expf(sw[w] - mx);
    float inv = 1.0f / s;
    float acc = 0.f;
    #pragma unroll
    for (int w = 0; w < SWIN; w++) {
        float p = expf(sw[w] - mx) * inv;
        acc += p * v[((size_t)(b * NTOK + pcs[w])) * DIMM + h * DHH + tid];
    }
    const float* gp = gate + ((size_t)(b * NTOK + i)) * 24 + h * 3;
    float oc = outc[(size_t)gi * DHH + tid];
    float os = outs[(size_t)gi * DHH + tid];
    attn[((size_t)(b * NTOK + i)) * DIMM + h * DHH + tid] =
        gp[0] * oc + gp[1] * os + gp[2] * acc;
}

// ---------------- classifier head ----------------
__global__ void head_kernel(const float* __restrict__ hb, const float* __restrict__ W,
                            const float* __restrict__ bias, float* __restrict__ out)
{
    int o = blockIdx.y * 256 + threadIdx.x;
    int b = blockIdx.x;
    if (o >= NCLS) return;
    const float* hr = hb + b * DIMM;
    float acc = bias[o];
    for (int d = 0; d < DIMM; d++) acc += hr[d] * W[(size_t)d * NCLS + o];
    out[(size_t)b * NCLS + o] = acc;
}

// ---------------- launch ----------------
static inline void launch_sgemm(const float* A, const float* W, const float* bias,
                                const float* res, float* C, int M, int Nn, int K, int act) {
    dim3 grid((Nn + 63) / 64, (M + 63) / 64);
    dim3 blk(16, 16);
    sgemm_kernel<<<grid, blk>>>(A, W, bias, res, C, M, Nn, K, act);
}

extern "C" void kernel_launch(void* const* d_in, const int* in_sizes, int n_in,
                              void* d_out, int out_size) {
    const float* img     = (const float*)d_in[0];
    const float* patch_w = (const float*)d_in[1];
    const float* patch_b = (const float*)d_in[2];
    const float* pos_emb = (const float*)d_in[3];
    const float* cls_tok = (const float*)d_in[4];
    const float* ln1_g   = (const float*)d_in[5];
    const float* ln1_b   = (const float*)d_in[6];
    const float* Wq      = (const float*)d_in[7];
    const float* Wk      = (const float*)d_in[8];
    const float* Wv      = (const float*)d_in[9];
    const float* Wg      = (const float*)d_in[10];
    const float* Wo      = (const float*)d_in[11];
    const float* kpe     = (const float*)d_in[12];
    const float* vpe     = (const float*)d_in[13];
    const float* Wkc     = (const float*)d_in[14];
    const float* Wvc     = (const float*)d_in[15];
    const float* ln2_g   = (const float*)d_in[16];
    const float* ln2_b   = (const float*)d_in[17];
    const float* ff_w1   = (const float*)d_in[18];
    const float* ff_b1   = (const float*)d_in[19];
    const float* ff_w2   = (const float*)d_in[20];
    const float* ff_b2   = (const float*)d_in[21];
    const float* hln_g   = (const float*)d_in[22];
    const float* hln_b   = (const float*)d_in[23];
    const float* head_w  = (const float*)d_in[24];
    const float* head_b  = (const float*)d_in[25];

    float *x, *h, *q, *k, *v, *gate, *ck, *cv, *outc, *outs, *attn, *mlp, *hb;
    int* selb;
    cudaGetSymbolAddress((void**)&x, g_x);
    cudaGetSymbolAddress((void**)&h, g_h);
    cudaGetSymbolAddress((void**)&q, g_q);
    cudaGetSymbolAddress((void**)&k, g_k);
    cudaGetSymbolAddress((void**)&v, g_v);
    cudaGetSymbolAddress((void**)&gate, g_gate);
    cudaGetSymbolAddress((void**)&ck, g_ck);
    cudaGetSymbolAddress((void**)&cv, g_cv);
    cudaGetSymbolAddress((void**)&outc, g_outc);
    cudaGetSymbolAddress((void**)&outs, g_outs);
    cudaGetSymbolAddress((void**)&selb, g_selb);
    cudaGetSymbolAddress((void**)&attn, g_attn);
    cudaGetSymbolAddress((void**)&mlp, g_mlp);
    cudaGetSymbolAddress((void**)&hb, g_hb);

    patch_embed_kernel<<<BB * NTOK, 256>>>(img, patch_w, patch_b, pos_emb, cls_tok, x);

    for (int l = 0; l < 2; l++) {
        const float* Wql = Wq + (size_t)l * DIMM * DIMM;
        const float* Wkl = Wk + (size_t)l * DIMM * DIMM;
        const float* Wvl = Wv + (size_t)l * DIMM * DIMM;
        const float* Wgl = Wg + (size_t)l * DIMM * 24;
        const float* Wol = Wo + (size_t)l * DIMM * DIMM;
        const float* kpel = kpe + (size_t)l * 16 * DHH;
        const float* vpel = vpe + (size_t)l * 16 * DHH;
        const float* Wkcl = Wkc + (size_t)l * 1024 * DHH;
        const float* Wvcl = Wvc + (size_t)l * 1024 * DHH;

        ln_kernel<<<BN, 256>>>(x, DIMM, h, ln1_g + l * DIMM, ln1_b + l * DIMM);

        launch_sgemm(h, Wql, nullptr, nullptr, q, BN, DIMM, DIMM, ACT_NONE);
        launch_sgemm(h, Wkl, nullptr, nullptr, k, BN, DIMM, DIMM, ACT_NONE);
        launch_sgemm(h, Wvl, nullptr, nullptr, v, BN, DIMM, DIMM, ACT_NONE);
        launch_sgemm(h, Wgl, nullptr, nullptr, gate, BN, 24, DIMM, ACT_SIG);

        compress_kernel<<<BB * HH * NCC, 64>>>(k, kpel, Wkcl, ck);
        compress_kernel<<<BB * HH * NCC, 64>>>(v, vpel, Wvcl, cv);

        cattn_kernel<<<BB * HH * NTOK, 256>>>(q, ck, cv, outc, selb);
        sattn_kernel<<<BB * HH * NTOK, 256>>>(q, k, v, selb, outs);
        wcomb_kernel<<<BB * HH * NTOK, 64>>>(q, k, v, outc, outs, gate, attn);

        launch_sgemm(attn, Wol, nullptr, x, x, BN, DIMM, DIMM, ACT_NONE);

        ln_kernel<<<BN, 256>>>(x, DIMM, h, ln2_g + l * DIMM, ln2_b + l * DIMM);
        launch_sgemm(h, ff_w1 + (size_t)l * DIMM * MLPD, ff_b1 + (size_t)l * MLPD,
                     nullptr, mlp, BN, MLPD, DIMM, ACT_GELU);
        launch_sgemm(mlp, ff_w2 + (size_t)l * MLPD * DIMM, ff_b2 + (size_t)l * DIMM,
                     x, x, BN, DIMM, MLPD, ACT_NONE);
    }

    // head: LN of token 0 of each batch, then linear
    ln_kernel<<<BB, 256>>>(x, (long)NTOK * DIMM, hb, hln_g, hln_b);
    head_kernel<<<dim3(BB, (NCLS + 255) / 256), 256>>>(hb, head_w, head_b, (float*)d_out);
}

// round 2
// speedup vs baseline: 2.2649x; 2.2649x over previous
#include <cuda_runtime.h>
#include <math.h>

// ---------------- problem constants ----------------
#define BB   2
#define NTOK 577
#define DIMM 512
#define HH   8
#define DHH  64
#define NCC  145     // ceil(577/4) compressed blocks
#define NSB  10      // ceil(577/64) select blocks
#define KSEL 4
#define SWIN 32
#define MLPD 2048
#define NCLS 1000
#define BN   (BB*NTOK)    // 1154
#define QC   8            // queries per cattn block
#define NQB  73           // ceil(577/8)
#define NJC  37           // ceil(145/4)

#define ACT_NONE 0
#define ACT_GELU 1
#define ACT_SIG  2

// ---------------- device scratch ----------------
__device__ float g_x   [BN*DIMM];
__device__ float g_h   [BN*DIMM];
__device__ float g_q   [BN*DIMM];
__device__ float g_k   [BN*DIMM];
__device__ float g_v   [BN*DIMM];
__device__ float g_gate[BN*24];
__device__ float g_ck  [BB*HH*NCC*DHH];
__device__ float g_cv  [BB*HH*NCC*DHH];
__device__ float g_outc[BB*HH*NTOK*DHH];
__device__ float g_outs[BB*HH*NTOK*DHH];
__device__ int   g_selb[BB*HH*NTOK*KSEL];
__device__ float g_attn[BN*DIMM];
__device__ float g_mlp [BN*MLPD];
__device__ float g_hb  [BB*DIMM];

// ---------------- helpers ----------------
__device__ __forceinline__ float gelu_tanh(float x) {
    float x3 = x * x * x;
    return 0.5f * x * (1.0f + tanhf(0.7978845608028654f * (x + 0.044715f * x3)));
}

// block-wide (256 threads) reductions via shfl + 8-slot smem
__device__ __forceinline__ float blk_max256(float v, float* sred) {
    #pragma unroll
    for (int o = 16; o; o >>= 1) v = fmaxf(v, __shfl_xor_sync(0xffffffffu, v, o));
    __syncthreads();
    if ((threadIdx.x & 31) == 0) sred[threadIdx.x >> 5] = v;
    __syncthreads();
    float r = sred[0];
    #pragma unroll
    for (int w = 1; w < 8; w++) r = fmaxf(r, sred[w]);
    return r;
}
__device__ __forceinline__ float blk_sum256(float v, float* sred) {
    #pragma unroll
    for (int o = 16; o; o >>= 1) v += __shfl_xor_sync(0xffffffffu, v, o);
    __syncthreads();
    if ((threadIdx.x & 31) == 0) sred[threadIdx.x >> 5] = v;
    __syncthreads();
    float r = sred[0];
    #pragma unroll
    for (int w = 1; w < 8; w++) r += sred[w];
    return r;
}

// ---------------- patch embed + cls + pos ----------------
__global__ void patch_embed_kernel(const float* __restrict__ img,
                                   const float* __restrict__ pw,
                                   const float* __restrict__ pb,
                                   const float* __restrict__ pos,
                                   const float* __restrict__ cls,
                                   float* __restrict__ x) {
    int t = blockIdx.x % NTOK;
    int b = blockIdx.x / NTOK;
    for (int d = threadIdx.x; d < DIMM; d += blockDim.x) {
        float v;
        if (t == 0) {
            v = cls[d];
        } else {
            int p = t - 1;
            int ii = p / 24, jj = p % 24;
            v = pb[d];
            #pragma unroll
            for (int c = 0; c < 3; c++)
                v += img[((b * 3 + c) * 24 + ii) * 24 + jj] * pw[c * DIMM + d];
        }
        x[((size_t)(b * NTOK + t)) * DIMM + d] = v + pos[(size_t)t * DIMM + d];
    }
}

// ---------------- layernorm (row length 512, block 256) ----------------
__global__ __launch_bounds__(256) void ln_kernel(const float* __restrict__ in, long strideIn,
                          float* __restrict__ out,
                          const float* __restrict__ g, const float* __restrict__ bb) {
    __shared__ float sred[8];
    int r = blockIdx.x;
    const float* row = in + (size_t)r * strideIn;
    int t = threadIdx.x;
    float a0 = row[t], a1 = row[t + 256];
    float mean = blk_sum256(a0 + a1, sred) * (1.0f / 512.0f);
    float d0 = a0 - mean, d1 = a1 - mean;
    __syncthreads();
    float var = blk_sum256(d0 * d0 + d1 * d1, sred) * (1.0f / 512.0f);
    float inv = rsqrtf(var + 1e-5f);
    out[(size_t)r * DIMM + t]       = d0 * inv * g[t] + bb[t];
    out[(size_t)r * DIMM + t + 256] = d1 * inv * g[t + 256] + bb[t + 256];
}

// ---------------- SGEMM core: 64x64 tile, 256 threads, 4x4/thread ----------------
// double-buffered smem, float4 global + shared accesses
__device__ __forceinline__ void gemm_core(
    const float* __restrict__ A, const float* __restrict__ W,
    const float* __restrict__ bias, const float* __restrict__ res,
    float* __restrict__ C, int M, int Nn, int K, int act, int row0, int col0)
{
    __shared__ __align__(16) float As[2][16][68];
    __shared__ __align__(16) float Bs[2][16][64];
    int tid = threadIdx.x;
    int tx = tid & 15, ty = tid >> 4;

    // A load meta: thread loads one float4 per k-step
    int am  = tid >> 2;       // row within tile 0..63
    int akq = tid & 3;        // k-quad 0..3
    int arow = row0 + am;
    const float* Aptr = (arow < M) ? (A + (size_t)arow * K + akq * 4) : (const float*)0;
    // B load meta
    int bkk = tid >> 4;       // 0..15
    int bnq = tid & 15;       // 0..15
    int bcol = col0 + bnq * 4;
    const float* Wptr = W + (size_t)bkk * Nn + bcol;
    bool bfull = (bcol + 3 < Nn);
    bool bany  = (bcol < Nn);

    float4 a4, b4;
    // prime k0 = 0
    if (Aptr) a4 = *(const float4*)(Aptr);
    else      a4 = make_float4(0.f, 0.f, 0.f, 0.f);
    if (bfull) b4 = *(const float4*)(Wptr);
    else {
        b4 = make_float4(0.f, 0.f, 0.f, 0.f);
        if (bany) {
            b4.x = Wptr[0];
            if (bcol + 1 < Nn) b4.y = Wptr[1];
            if (bcol + 2 < Nn) b4.z = Wptr[2];
        }
    }
    As[0][akq * 4 + 0][am] = a4.x;
    As[0][akq * 4 + 1][am] = a4.y;
    As[0][akq * 4 + 2][am] = a4.z;
    As[0][akq * 4 + 3][am] = a4.w;
    *(float4*)&Bs[0][bkk][bnq * 4] = b4;
    __syncthreads();

    float acc[4][4];
    #pragma unroll
    for (int i = 0; i < 4; i++)
        #pragma unroll
        for (int j = 0; j < 4; j++) acc[i][j] = 0.f;

    int steps = K >> 4;
    for (int ks = 0; ks < steps; ks++) {
        int cur = ks & 1;
        bool hn = (ks + 1 < steps);
        if (hn) {
            int k0 = (ks + 1) * 16;
            if (Aptr) a4 = *(const float4*)(Aptr + k0);
            else      a4 = make_float4(0.f, 0.f, 0.f, 0.f);
            if (bfull) b4 = *(const float4*)(Wptr + (size_t)k0 * Nn);
            else {
                b4 = make_float4(0.f, 0.f, 0.f, 0.f);
                if (bany) {
                    const float* p = Wptr + (size_t)k0 * Nn;
                    b4.x = p[0];
                    if (bcol + 1 < Nn) b4.y = p[1];
                    if (bcol + 2 < Nn) b4.z = p[2];
                }
            }
        }
        #pragma unroll
        for (int kk = 0; kk < 16; kk++) {
            float4 av = *(const float4*)&As[cur][kk][ty * 4];
            float4 bv = *(const float4*)&Bs[cur][kk][tx * 4];
            acc[0][0] += av.x * bv.x; acc[0][1] += av.x * bv.y; acc[0][2] += av.x * bv.z; acc[0][3] += av.x * bv.w;
            acc[1][0] += av.y * bv.x; acc[1][1] += av.y * bv.y; acc[1][2] += av.y * bv.z; acc[1][3] += av.y * bv.w;
            acc[2][0] += av.z * bv.x; acc[2][1] += av.z * bv.y; acc[2][2] += av.z * bv.z; acc[2][3] += av.z * bv.w;
            acc[3][0] += av.w * bv.x; acc[3][1] += av.w * bv.y; acc[3][2] += av.w * bv.z; acc[3][3] += av.w * bv.w;
        }
        if (hn) {
            int nxt = cur ^ 1;
            As[nxt][akq * 4 + 0][am] = a4.x;
            As[nxt][akq * 4 + 1][am] = a4.y;
            As[nxt][akq * 4 + 2][am] = a4.z;
            As[nxt][akq * 4 + 3][am] = a4.w;
            *(float4*)&Bs[nxt][bkk][bnq * 4] = b4;
            __syncthreads();
        }
    }
    #pragma unroll
    for (int i = 0; i < 4; i++) {
        int r = row0 + ty * 4 + i;
        if (r >= M) continue;
        #pragma unroll
        for (int j = 0; j < 4; j++) {
            int c = col0 + tx * 4 + j;
            if (c >= Nn) continue;
            float v = acc[i][j];
            if (bias) v += bias[c];
            if (act == ACT_GELU) v = gelu_tanh(v);
            else if (act == ACT_SIG) v = 1.0f / (1.0f + expf(-v));
            if (res) v += res[(size_t)r * Nn + c];
            C[(size_t)r * Nn + c] = v;
        }
    }
}

__global__ __launch_bounds__(256) void sgemm_kernel(
    const float* __restrict__ A, const float* __restrict__ W,
    const float* __restrict__ bias, const float* __restrict__ res,
    float* __restrict__ C, int M, int Nn, int K, int act)
{
    gemm_core(A, W, bias, res, C, M, Nn, K, act, blockIdx.y * 64, blockIdx.x * 64);
}

// fused QKV + gate projection
__global__ __launch_bounds__(256) void qkvg_kernel(
    const float* __restrict__ h,
    const float* __restrict__ Wq, const float* __restrict__ Wk,
    const float* __restrict__ Wv, const float* __restrict__ Wg,
    float* __restrict__ q, float* __restrict__ k,
    float* __restrict__ v, float* __restrict__ gate)
{
    int bx = blockIdx.x;
    const float* W; float* C; int Nn, col0, act = ACT_NONE;
    if (bx < 8)       { W = Wq; C = q;    Nn = 512; col0 = bx * 64; }
    else if (bx < 16) { W = Wk; C = k;    Nn = 512; col0 = (bx - 8) * 64; }
    else if (bx < 24) { W = Wv; C = v;    Nn = 512; col0 = (bx - 16) * 64; }
    else              { W = Wg; C = gate; Nn = 24;  col0 = 0; act = ACT_SIG; }
    gemm_core(h, W, (const float*)0, (const float*)0, C, BN, Nn, 512, act,
              blockIdx.y * 64, col0);
}

// ---------------- compress projection (k and v fused via blockIdx.y) ----------------
__global__ __launch_bounds__(256) void compress_kernel(
    const float* __restrict__ kin, const float* __restrict__ vin,
    const float* __restrict__ kpe, const float* __restrict__ vpe,
    const float* __restrict__ Wkc, const float* __restrict__ Wvc,
    float* __restrict__ cko, float* __restrict__ cvo)
{
    const float* in; const float* pe; const float* Wc; float* out;
    if (blockIdx.y == 0) { in = kin; pe = kpe; Wc = Wkc; out = cko; }
    else                 { in = vin; pe = vpe; Wc = Wvc; out = cvo; }
    __shared__ float kw[4][1024];
    __shared__ float part[4][4][64];
    int bx = blockIdx.x;
    int jc = bx % NJC, bh = bx / NJC;
    int h = bh % HH, b = bh / HH;
    int tid = threadIdx.x;
    for (int idx = tid; idx < 4096; idx += 256) {
        int jl = idx >> 10, e = idx & 1023;
        int jj = e >> 6, d = e & 63;
        int j = jc * 4 + jl;
        int tok = j * 4 + jj;
        float val = (j < NCC && tok < NTOK)
            ? in[((size_t)(b * NTOK + tok)) * DIMM + h * DHH + d] : 0.f;
        kw[jl][e] = val + pe[e];
    }
    __syncthreads();
    int es = tid >> 6, d = tid & 63;
    float a0 = 0.f, a1 = 0.f, a2 = 0.f, a3 = 0.f;
    int e0 = es * 256;
    for (int e = e0; e < e0 + 256; e++) {
        float wv = Wc[(size_t)e * 64 + d];
        a0 += kw[0][e] * wv; a1 += kw[1][e] * wv;
        a2 += kw[2][e] * wv; a3 += kw[3][e] * wv;
    }
    part[0][es][d] = a0; part[1][es][d] = a1;
    part[2][es][d] = a2; part[3][es][d] = a3;
    __syncthreads();
    int jl = tid >> 6;
    int j = jc * 4 + jl;
    if (j < NCC) {
        out[((size_t)(bh * NCC + j)) * 64 + d] =
            part[jl][0][d] + part[jl][1][d] + part[jl][2][d] + part[jl][3][d];
    }
}

// ---------------- compressed attention + top-k (8 queries/block) ----------------
__global__ __launch_bounds__(256) void cattn_kernel(
    const float* __restrict__ q, const float* __restrict__ ck,
    const float* __restrict__ cv, float* __restrict__ outc,
    int* __restrict__ selb)
{
    __shared__ float cbuf[NCC * 65];   // 37700 B
    __shared__ float qs[QC * 64];      // 2048 B
    __shared__ float sc[QC][NCC];      // 4640 B
    int blk = blockIdx.x;
    int qb = blk % NQB, bh = blk / NQB;
    int h = bh % HH, b = bh / HH;
    int i0 = qb * QC;
    int tid = threadIdx.x;
    for (int idx = tid; idx < QC * 64; idx += 256) {
        int u = idx >> 6, d2 = idx & 63, i = i0 + u;
        qs[idx] = (i < NTOK) ? q[((size_t)(b * NTOK + i)) * DIMM + h * DHH + d2] : 0.f;
    }
    const float* ckb = ck + (size_t)bh * NCC * DHH;
    for (int idx = tid; idx < NCC * 64; idx += 256) {
        int j = idx >> 6, d2 = idx & 63;
        cbuf[j * 65 + d2] = ckb[idx];
    }
    __syncthreads();
    for (int p = tid; p < QC * NCC; p += 256) {
        int u = p / NCC, j = p % NCC;
        const float* cr = &cbuf[j * 65];
        const float* qr = &qs[u * 64];
        float a = 0.f;
        #pragma unroll
        for (int d2 = 0; d2 < 64; d2++) a += qr[d2] * cr[d2];
        sc[u][j] = a * 0.125f;
    }
    __syncthreads();
    // warp-per-query softmax
    int w = tid >> 5, ln = tid & 31;
    {
        float m = -1e30f;
        for (int j = ln; j < NCC; j += 32) m = fmaxf(m, sc[w][j]);
        #pragma unroll
        for (int o = 16; o; o >>= 1) m = fmaxf(m, __shfl_xor_sync(0xffffffffu, m, o));
        float s = 0.f;
        for (int j = ln; j < NCC; j += 32) { float e = expf(sc[w][j] - m); sc[w][j] = e; s += e; }
        #pragma unroll
        for (int o = 16; o; o >>= 1) s += __shfl_xor_sync(0xffffffffu, s, o);
        float inv = 1.f / s;
        for (int j = ln; j < NCC; j += 32) sc[w][j] *= inv;
    }
    __syncthreads();
    // top-k select (thread per query)
    if (tid < QC) {
        int i = i0 + tid;
        if (i < NTOK) {
            float imp[NSB];
            #pragma unroll
            for (int t = 0; t < NSB; t++) imp[t] = 0.f;
            for (int j = 0; j < NCC; j++) {
                int c = (j + 2) >> 4; if (c > NSB - 1) c = NSB - 1;
                imp[c] += sc[tid][j];
            }
            size_t gi = (size_t)bh * NTOK + i;
            #pragma unroll
            for (int t = 0; t < KSEL; t++) {
                float best = -1e30f; int bi = 0;
                #pragma unroll
                for (int sbv = 0; sbv < NSB; sbv++)
                    if (imp[sbv] > best) { best = imp[sbv]; bi = sbv; }
                selb[gi * KSEL + t] = bi;
                imp[bi] = -2e30f;
            }
        }
    }
    __syncthreads();
    // PV phase: reload cbuf with cv
    const float* cvb = cv + (size_t)bh * NCC * DHH;
    for (int idx = tid; idx < NCC * 64; idx += 256) {
        int j = idx >> 6, d2 = idx & 63;
        cbuf[j * 65 + d2] = cvb[idx];
    }
    __syncthreads();
    for (int p = tid; p < QC * 64; p += 256) {
        int u = p >> 6, d2 = p & 63;
        int i = i0 + u;
        if (i >= NTOK) continue;
        float a = 0.f;
        for (int j = 0; j < NCC; j++) a += sc[u][j] * cbuf[j * 65 + d2];
        outc[((size_t)(bh * NTOK + i)) * 64 + d2] = a;
    }
}

// ---------------- selected-block attention (256 threads, smem-staged) ----------------
__global__ __launch_bounds__(256) void sattn_kernel(
    const float* __restrict__ q, const float* __restrict__ k,
    const float* __restrict__ v, const int* __restrict__ selb,
    float* __restrict__ outs)
{
    __shared__ float qs[64];
    __shared__ float kv[64 * 65];
    __shared__ float ss[256];
    __shared__ float part[256];
    __shared__ float sred[8];
    __shared__ int sb[4];
    int gi = blockIdx.x;
    int i = gi % NTOK;
    int bh = gi / NTOK;
    int h = bh % HH, b = bh / HH;
    int tid = threadIdx.x;
    if (tid < 64) qs[tid] = q[((size_t)(b * NTOK + i)) * DIMM + h * DHH + tid];
    if (tid < 4) sb[tid] = selb[(size_t)gi * KSEL + tid];
    __syncthreads();
    const float* kbase = k + (size_t)b * NTOK * DIMM + h * DHH;
    int tt = tid & 63, ds = tid >> 6;
    for (int c = 0; c < 4; c++) {
        int blk = sb[c];
        for (int idx = tid; idx < 4096; idx += 256) {
            int t2 = idx >> 6, d2 = idx & 63;
            int tok = blk * 64 + t2; int tk = tok < NTOK ? tok : NTOK - 1;
            kv[t2 * 65 + d2] = kbase[(size_t)tk * DIMM + d2];
        }
        __syncthreads();
        float pp = 0.f;
        #pragma unroll
        for (int d = 0; d < 16; d++) pp += qs[ds * 16 + d] * kv[tt * 65 + ds * 16 + d];
        part[tid] = pp;
        __syncthreads();
        if (tid < 64) {
            float a = part[tid] + part[tid + 64] + part[tid + 128] + part[tid + 192];
            int tok = blk * 64 + tid;
            ss[c * 64 + tid] = (tok < NTOK) ? a * 0.125f : -1e30f;
        }
        __syncthreads();
    }
    float sv = ss[tid];
    float mx = blk_max256(sv, sred);
    float e = expf(sv - mx);
    __syncthreads();
    float tot = blk_sum256(e, sred);
    ss[tid] = e / tot;
    __syncthreads();
    const float* vbase = v + (size_t)b * NTOK * DIMM + h * DHH;
    int d = tid & 63; int ts = tid >> 6;
    float acc = 0.f;
    for (int c = 0; c < 4; c++) {
        int blk = sb[c];
        for (int idx = tid; idx < 4096; idx += 256) {
            int t2 = idx >> 6, d2 = idx & 63;
            int tok = blk * 64 + t2; int tk = tok < NTOK ? tok : NTOK - 1;
            kv[t2 * 65 + d2] = vbase[(size_t)tk * DIMM + d2];
        }
        __syncthreads();
        #pragma unroll
        for (int t = 0; t < 16; t++)
            acc += ss[c * 64 + ts * 16 + t] * kv[(ts * 16 + t) * 65 + d];
        __syncthreads();
    }
    part[tid] = acc;
    __syncthreads();
    if (tid < 64)
        outs[(size_t)gi * 64 + tid] =
            part[tid] + part[tid + 64] + part[tid + 128] + part[tid + 192];
}

// ---------------- sliding window attention + gate combine (256 threads) ----------------
__global__ __launch_bounds__(256) void wcomb_kernel(
    const float* __restrict__ q, const float* __restrict__ k,
    const float* __restrict__ v,
    const float* __restrict__ outc, const float* __restrict__ outs,
    const float* __restrict__ gate, float* __restrict__ attn)
{
    __shared__ float qs[64];
    __shared__ float sw[SWIN];
    __shared__ int   pcs[SWIN];
    __shared__ float part[256];
    int gi = blockIdx.x;
    int i = gi % NTOK;
    int bh = gi / NTOK;
    int h = bh % HH, b = bh / HH;
    int tid = threadIdx.x;
    if (tid < 64) qs[tid] = q[((size_t)(b * NTOK + i)) * DIMM + h * DHH + tid];
    __syncthreads();
    if (tid < SWIN) {
        int pos = i + tid - SWIN / 2;
        bool valid = (pos >= 0) && (pos < NTOK);
        int p = pos < 0 ? 0 : (pos > NTOK - 1 ? NTOK - 1 : pos);
        pcs[tid] = p;
        const float* kp = k + ((size_t)(b * NTOK + p)) * DIMM + h * DHH;
        float a = 0.f;
        #pragma unroll
        for (int d = 0; d < 64; d++) a += qs[d] * kp[d];
        float s = valid ? a * 0.125f : -1e30f;
        float mx = s;
        #pragma unroll
        for (int o = 16; o; o >>= 1) mx = fmaxf(mx, __shfl_xor_sync(0xffffffffu, mx, o));
        float e = expf(s - mx);
        float tot = e;
        #pragma unroll
        for (int o = 16; o; o >>= 1) tot += __shfl_xor_sync(0xffffffffu, tot, o);
        sw[tid] = e / tot;
    }
    __syncthreads();
    int ws = tid >> 6, d = tid & 63;
    const float* vbase = v + (size_t)b * NTOK * DIMM + h * DHH;
    float pp = 0.f;
    #pragma unroll
    for (int w2 = 0; w2 < 8; w2++) {
        int w = ws * 8 + w2;
        pp += sw[w] * vbase[(size_t)pcs[w] * DIMM + d];
    }
    part[tid] = pp;
    __syncthreads();
    if (tid < 64) {
        float ow = part[tid] + part[tid + 64] + part[tid + 128] + part[tid + 192];
        const float* gp = gate + ((size_t)(b * NTOK + i)) * 24 + h * 3;
        float oc = outc[(size_t)gi * 64 + tid];
        float os = outs[(size_t)gi * 64 + tid];
        attn[((size_t)(b * NTOK + i)) * DIMM + h * DHH + tid] =
            gp[0] * oc + gp[1] * os + gp[2] * ow;
    }
}

// ---------------- classifier head ----------------
__global__ void head_kernel(const float* __restrict__ hb, const float* __restrict__ W,
                            const float* __restrict__ bias, float* __restrict__ out)
{
    int o = blockIdx.y * 256 + threadIdx.x;
    int b = blockIdx.x;
    if (o >= NCLS) return;
    const float* hr = hb + b * DIMM;
    float acc = bias[o];
    for (int d = 0; d < DIMM; d++) acc += hr[d] * W[(size_t)d * NCLS + o];
    out[(size_t)b * NCLS + o] = acc;
}

// ---------------- launch ----------------
static inline void launch_sgemm(const float* A, const float* W, const float* bias,
                                const float* res, float* C, int M, int Nn, int K, int act) {
    dim3 grid((Nn + 63) / 64, (M + 63) / 64);
    sgemm_kernel<<<grid, 256>>>(A, W, bias, res, C, M, Nn, K, act);
}

extern "C" void kernel_launch(void* const* d_in, const int* in_sizes, int n_in,
                              void* d_out, int out_size) {
    const float* img     = (const float*)d_in[0];
    const float* patch_w = (const float*)d_in[1];
    const float* patch_b = (const float*)d_in[2];
    const float* pos_emb = (const float*)d_in[3];
    const float* cls_tok = (const float*)d_in[4];
    const float* ln1_g   = (const float*)d_in[5];
    const float* ln1_b   = (const float*)d_in[6];
    const float* Wq      = (const float*)d_in[7];
    const float* Wk      = (const float*)d_in[8];
    const float* Wv      = (const float*)d_in[9];
    const float* Wg      = (const float*)d_in[10];
    const float* Wo      = (const float*)d_in[11];
    const float* kpe     = (const float*)d_in[12];
    const float* vpe     = (const float*)d_in[13];
    const float* Wkc     = (const float*)d_in[14];
    const float* Wvc     = (const float*)d_in[15];
    const float* ln2_g   = (const float*)d_in[16];
    const float* ln2_b   = (const float*)d_in[17];
    const float* ff_w1   = (const float*)d_in[18];
    const float* ff_b1   = (const float*)d_in[19];
    const float* ff_w2   = (const float*)d_in[20];
    const float* ff_b2   = (const float*)d_in[21];
    const float* hln_g   = (const float*)d_in[22];
    const float* hln_b   = (const float*)d_in[23];
    const float* head_w  = (const float*)d_in[24];
    const float* head_b  = (const float*)d_in[25];

    float *x, *h, *q, *k, *v, *gate, *ck, *cv, *outc, *outs, *attn, *mlp, *hb;
    int* selb;
    cudaGetSymbolAddress((void**)&x, g_x);
    cudaGetSymbolAddress((void**)&h, g_h);
    cudaGetSymbolAddress((void**)&q, g_q);
    cudaGetSymbolAddress((void**)&k, g_k);
    cudaGetSymbolAddress((void**)&v, g_v);
    cudaGetSymbolAddress((void**)&gate, g_gate);
    cudaGetSymbolAddress((void**)&ck, g_ck);
    cudaGetSymbolAddress((void**)&cv, g_cv);
    cudaGetSymbolAddress((void**)&outc, g_outc);
    cudaGetSymbolAddress((void**)&outs, g_outs);
    cudaGetSymbolAddress((void**)&selb, g_selb);
    cudaGetSymbolAddress((void**)&attn, g_attn);
    cudaGetSymbolAddress((void**)&mlp, g_mlp);
    cudaGetSymbolAddress((void**)&hb, g_hb);

    patch_embed_kernel<<<BB * NTOK, 256>>>(img, patch_w, patch_b, pos_emb, cls_tok, x);

    for (int l = 0; l < 2; l++) {
        const float* Wql = Wq + (size_t)l * DIMM * DIMM;
        const float* Wkl = Wk + (size_t)l * DIMM * DIMM;
        const float* Wvl = Wv + (size_t)l * DIMM * DIMM;
        const float* Wgl = Wg + (size_t)l * DIMM * 24;
        const float* Wol = Wo + (size_t)l * DIMM * DIMM;
        const float* kpel = kpe + (size_t)l * 16 * DHH;
        const float* vpel = vpe + (size_t)l * 16 * DHH;
        const float* Wkcl = Wkc + (size_t)l * 1024 * DHH;
        const float* Wvcl = Wvc + (size_t)l * 1024 * DHH;

        ln_kernel<<<BN, 256>>>(x, DIMM, h, ln1_g + l * DIMM, ln1_b + l * DIMM);

        qkvg_kernel<<<dim3(25, 19), 256>>>(h, Wql, Wkl, Wvl, Wgl, q, k, v, gate);

        compress_kernel<<<dim3(BB * HH * NJC, 2), 256>>>(k, v, kpel, vpel, Wkcl, Wvcl, ck, cv);

        cattn_kernel<<<BB * HH * NQB, 256>>>(q, ck, cv, outc, selb);
        sattn_kernel<<<BB * HH * NTOK, 256>>>(q, k, v, selb, outs);
        wcomb_kernel<<<BB * HH * NTOK, 256>>>(q, k, v, outc, outs, gate, attn);

        launch_sgemm(attn, Wol, nullptr, x, x, BN, DIMM, DIMM, ACT_NONE);

        ln_kernel<<<BN, 256>>>(x, DIMM, h, ln2_g + l * DIMM, ln2_b + l * DIMM);
        launch_sgemm(h, ff_w1 + (size_t)l * DIMM * MLPD, ff_b1 + (size_t)l * MLPD,
                     nullptr, mlp, BN, MLPD, DIMM, ACT_GELU);
        launch_sgemm(mlp, ff_w2 + (size_t)l * MLPD * DIMM, ff_b2 + (size_t)l * DIMM,
                     x, x, BN, DIMM, MLPD, ACT_NONE);
    }

    ln_kernel<<<BB, 256>>>(x, (long)NTOK * DIMM, hb, hln_g, hln_b);
    head_kernel<<<dim3(BB, (NCLS + 255) / 256), 256>>>(hb, head_w, head_b, (float*)d_out);
}